// round 4
// baseline (speedup 1.0000x reference)
#include <cuda_runtime.h>
#include <math.h>

#define BB 16
#define TT 8192
#define DD 128
#define CC 64
#define NN 128          // TT / CC

// Scratch: per-chunk weighted outer products (overwritten in-place by the
// exclusive prefix state scan) and per-chunk decayed k-sums (then z-scan).
__device__ float g_W[(size_t)BB * NN * DD * DD];   // 134 MB
__device__ float g_ks[(size_t)BB * NN * DD];       // 1 MB

__device__ __forceinline__ float sigmoidf_(float x) { return 1.0f / (1.0f + expf(-x)); }

// ---- packed fp32x2 helpers (full fp32 precision, 2 FMA per issue slot) ----
typedef unsigned long long u64t;

__device__ __forceinline__ u64t splat2(float a) {
    u64t r; asm("mov.b64 %0, {%1, %1};" : "=l"(r) : "f"(a)); return r;
}
__device__ __forceinline__ void ffma2(u64t& d, u64t a, u64t b) {
    asm("fma.rn.f32x2 %0, %1, %2, %3;" : "=l"(d) : "l"(a), "l"(b), "l"(d));
}
__device__ __forceinline__ void fmul2(u64t& d, u64t a) {
    asm("mul.rn.f32x2 %0, %1, %2;" : "=l"(d) : "l"(d), "l"(a));
}
__device__ __forceinline__ float2 unpack2(u64t p) {
    float2 f; asm("mov.b64 {%0, %1}, %2;" : "=f"(f.x), "=f"(f.y) : "l"(p)); return f;
}

// ---------------------------------------------------------------------------
// Pass 1: per-chunk W_n[i][j] = sum_c lam^(C-1-c) k[c][i] v[c][j]
//         and ks_n[i] = sum_c lam^(C-1-c) k[c][i]
// grid = B*N blocks, 256 threads, 64 KB dynamic smem
// Thread tile: 8 i-rows x 8 j-cols (two 4-wide groups), FFMA2-packed along j.
// ---------------------------------------------------------------------------
__global__ void __launch_bounds__(256)
pass1_kernel(const float* __restrict__ k, const float* __restrict__ v,
             const float* __restrict__ logd)
{
    int b = blockIdx.x >> 7;
    int n = blockIdx.x & 127;
    extern __shared__ float sm[];
    float* kd = sm;            // [CC][DD] k premultiplied by chunk_decay
    float* vs = sm + CC * DD;  // [CC][DD]
    __shared__ float powl[CC + 1];
    int tid = threadIdx.x;
    if (tid == 0) {
        float lam = sigmoidf_(logd[0]);
        float p = 1.0f;
        for (int i = 0; i <= CC; i++) { powl[i] = p; p *= lam; }
    }
    __syncthreads();

    const float* kg = k + ((size_t)b * TT + (size_t)n * CC) * DD;
    const float* vg = v + ((size_t)b * TT + (size_t)n * CC) * DD;
    for (int idx = tid; idx < CC * DD; idx += 256) {
        int c = idx >> 7;
        kd[idx] = kg[idx] * powl[CC - 1 - c];
        vs[idx] = vg[idx];
    }
    __syncthreads();

    // ks
    if (tid < DD) {
        float s = 0.0f;
        for (int c = 0; c < CC; c++) s += kd[c * DD + tid];
        g_ks[((size_t)b * NN + n) * DD + tid] = s;
    }

    int i0 = (tid >> 4) * 8;
    int jt = tid & 15;
    int jA = jt * 4, jB = 64 + jt * 4;

    u64t acc[8][4];
#pragma unroll
    for (int u = 0; u < 8; u++)
#pragma unroll
        for (int w = 0; w < 4; w++) acc[u][w] = 0ull;

    for (int c = 0; c < CC; c++) {
        ulonglong2 bA = *(const ulonglong2*)&vs[c * DD + jA];
        ulonglong2 bB = *(const ulonglong2*)&vs[c * DD + jB];
        float4 a0 = *(const float4*)&kd[c * DD + i0];
        float4 a1 = *(const float4*)&kd[c * DD + i0 + 4];
        float av[8] = {a0.x, a0.y, a0.z, a0.w, a1.x, a1.y, a1.z, a1.w};
#pragma unroll
        for (int u = 0; u < 8; u++) {
            u64t s = splat2(av[u]);
            ffma2(acc[u][0], s, bA.x);
            ffma2(acc[u][1], s, bA.y);
            ffma2(acc[u][2], s, bB.x);
            ffma2(acc[u][3], s, bB.y);
        }
    }

    float* Wg = g_W + (size_t)blockIdx.x * DD * DD;  // blockIdx.x == b*NN + n
#pragma unroll
    for (int u = 0; u < 8; u++) {
        float2 p0 = unpack2(acc[u][0]), p1 = unpack2(acc[u][1]);
        float2 p2 = unpack2(acc[u][2]), p3 = unpack2(acc[u][3]);
        float4 oA = {p0.x, p0.y, p1.x, p1.y};
        float4 oB = {p2.x, p2.y, p3.x, p3.y};
        *(float4*)&Wg[(i0 + u) * DD + jA] = oA;
        *(float4*)&Wg[(i0 + u) * DD + jB] = oB;
    }
}

// ---------------------------------------------------------------------------
// Pass 2a: in-place exclusive prefix scan of W -> state-before-chunk-n.
// ---------------------------------------------------------------------------
__global__ void __launch_bounds__(256)
pass2_state_kernel(const float* __restrict__ logd, float* __restrict__ out_state,
                   int write_final)
{
    int idx = blockIdx.x * 256 + threadIdx.x;   // < BB*DD*DD = 262144
    float lam = sigmoidf_(logd[0]);
    float dc = lam;
#pragma unroll
    for (int i = 0; i < 6; i++) dc *= dc;       // lam^64
    int b = idx >> 14;
    int e = idx & 16383;
    size_t base = (size_t)b * NN * DD * DD + e;
    float s = 0.0f;
#pragma unroll 4
    for (int n = 0; n < NN; n++) {
        size_t off = base + (size_t)n * DD * DD;
        float w = g_W[off];
        g_W[off] = s;
        s = dc * s + w;
    }
    if (write_final) out_state[idx] = s;
}

// Pass 2b: same scan for z (ks scratch). One thread per (b,i).
__global__ void __launch_bounds__(256)
pass2_z_kernel(const float* __restrict__ logd, float* __restrict__ out_z,
               int write_final)
{
    int idx = blockIdx.x * 256 + threadIdx.x;   // < BB*DD = 2048
    float lam = sigmoidf_(logd[0]);
    float dc = lam;
#pragma unroll
    for (int i = 0; i < 6; i++) dc *= dc;
    int b = idx >> 7;
    int e = idx & 127;
    size_t base = (size_t)b * NN * DD + e;
    float s = 0.0f;
#pragma unroll 4
    for (int n = 0; n < NN; n++) {
        size_t off = base + (size_t)n * DD;
        float w = g_ks[off];
        g_ks[off] = s;
        s = dc * s + w;
    }
    if (write_final) out_z[idx] = s;
}

// ---------------------------------------------------------------------------
// Pass 3: intra-chunk causal attention + cross-chunk state read + normalize.
// grid = B*N blocks, 256 threads.
// Shared layout (floats):
//   qs   [64][132]   q tile
//   kT   [128][68]   k transposed (for packed QK); later reused as v [64][136]
//   attn [64][68]
// ---------------------------------------------------------------------------
#define QS 132
#define KTS 68
#define VS 136
#define AS 68
#define P3_SMEM ((CC * QS + DD * KTS + CC * AS) * sizeof(float))

__global__ void __launch_bounds__(256)
pass3_kernel(const float* __restrict__ q, const float* __restrict__ k,
             const float* __restrict__ v, const float* __restrict__ logd,
             float* __restrict__ out)
{
    int b = blockIdx.x >> 7;
    int n = blockIdx.x & 127;
    extern __shared__ float sm[];
    float* qs   = sm;                       // [CC][QS]
    float* kT   = sm + CC * QS;             // [DD][KTS]  (later v [CC][VS])
    float* attn = sm + CC * QS + DD * KTS;  // [CC][AS]
    float* vv   = kT;                       // v reuses kT region: 64*136 = 128*68
    __shared__ float powl[CC + 1];
    __shared__ float iz[CC];
    __shared__ float cz[CC];
    __shared__ float czp[CC][4];
    int tid = threadIdx.x;
    if (tid == 0) {
        float lam = sigmoidf_(logd[0]);
        float p = 1.0f;
        for (int i = 0; i <= CC; i++) { powl[i] = p; p *= lam; }
    }

    const float* qg = q + ((size_t)b * TT + (size_t)n * CC) * DD;
    const float* kg = k + ((size_t)b * TT + (size_t)n * CC) * DD;
    for (int idx = tid; idx < CC * DD; idx += 256) {
        int c = idx >> 7, d = idx & 127;
        qs[c * QS + d] = qg[idx];
        kT[d * KTS + c] = kg[idx];
    }
    __syncthreads();

    // ---- QK^T: attn[c][j] = (j<=c) ? (q_c . k_j) * lam^(c-j) : 0
    // thread tile 4c x 4j, FFMA2-packed along j.
    {
        int c0 = (tid >> 4) * 4;
        int j0 = (tid & 15) * 4;
        u64t accq[4][2];
#pragma unroll
        for (int u = 0; u < 4; u++) { accq[u][0] = 0ull; accq[u][1] = 0ull; }

        for (int d = 0; d < DD; d += 2) {
            ulonglong2 kA = *(const ulonglong2*)&kT[(d + 0) * KTS + j0];
            ulonglong2 kB = *(const ulonglong2*)&kT[(d + 1) * KTS + j0];
#pragma unroll
            for (int u = 0; u < 4; u++) {
                float2 qa = *(const float2*)&qs[(c0 + u) * QS + d];
                u64t s0 = splat2(qa.x), s1 = splat2(qa.y);
                ffma2(accq[u][0], s0, kA.x);
                ffma2(accq[u][1], s0, kA.y);
                ffma2(accq[u][0], s1, kB.x);
                ffma2(accq[u][1], s1, kB.y);
            }
        }
#pragma unroll
        for (int u = 0; u < 4; u++) {
            int c = c0 + u;
            float2 p0 = unpack2(accq[u][0]);
            float2 p1 = unpack2(accq[u][1]);
            float vals[4] = {p0.x, p0.y, p1.x, p1.y};
            float4 row;
            float* rp = (float*)&row;
#pragma unroll
            for (int w = 0; w < 4; w++) {
                int j = j0 + w;
                rp[w] = (j <= c) ? vals[w] * powl[c - j] : 0.0f;
            }
            *(float4*)&attn[c * AS + j0] = row;
        }
    }
    __syncthreads();   // attn visible; kT reads done -> safe to overwrite with v

    // ---- load v (into kT region, stride VS) and cz partials
    {
        const float* vg = v + ((size_t)b * TT + (size_t)n * CC) * DD;
        for (int idx = tid; idx < CC * DD; idx += 256) {
            int c = idx >> 7, d = idx & 127;
            vv[c * VS + d] = vg[idx];
        }
        const float* zg = g_ks + ((size_t)b * NN + n) * DD;  // z before chunk n
        int c = tid >> 2, qtr = tid & 3;
        float cs = 0.0f;
        for (int i = qtr * 32; i < qtr * 32 + 32; i++)
            cs += zg[i] * qs[c * QS + i];
        czp[c][qtr] = cs;
    }
    __syncthreads();

    // ---- iz (clamped row sums) and cz
    if (tid < CC) {
        int c = tid;
        float s = 0.0f;
        for (int j = 0; j <= c; j++) s += attn[c * AS + j];
        iz[c] = fmaxf(s, 1.0f);
        cz[c] = (czp[c][0] + czp[c][1] + czp[c][2] + czp[c][3]) * powl[c + 1];
    }
    __syncthreads();

    // ---- main GEMM: out[c][d] = (decay_q[c] * sum_i q[c][i]*S[i][d]
    //                              + sum_j attn[c][j]*v[j][d]) / tz[c]
    // thread tile: 4 c-rows x 8 d-cols (two 4-wide groups dA, dB)
    int ct = tid >> 4, dt = tid & 15;
    int c0 = ct * 4;
    int dA = dt * 4, dB = 64 + dt * 4;

    u64t acc[4][4];
#pragma unroll
    for (int u = 0; u < 4; u++)
#pragma unroll
        for (int w = 0; w < 4; w++) acc[u][w] = 0ull;

    const float* S = g_W + (size_t)blockIdx.x * DD * DD;  // state before chunk n
    for (int i = 0; i < DD; i++) {
        ulonglong2 sA = *(const ulonglong2*)&S[i * DD + dA];
        ulonglong2 sB = *(const ulonglong2*)&S[i * DD + dB];
#pragma unroll
        for (int u = 0; u < 4; u++) {
            u64t qq = splat2(qs[(c0 + u) * QS + i]);
            ffma2(acc[u][0], qq, sA.x);
            ffma2(acc[u][1], qq, sA.y);
            ffma2(acc[u][2], qq, sB.x);
            ffma2(acc[u][3], qq, sB.y);
        }
    }
#pragma unroll
    for (int u = 0; u < 4; u++) {
        u64t dq = splat2(powl[c0 + u + 1]);   // decay_q
        fmul2(acc[u][0], dq); fmul2(acc[u][1], dq);
        fmul2(acc[u][2], dq); fmul2(acc[u][3], dq);
    }

    for (int j = 0; j < CC; j += 4) {
        ulonglong2 vA0 = *(const ulonglong2*)&vv[(j + 0) * VS + dA];
        ulonglong2 vB0 = *(const ulonglong2*)&vv[(j + 0) * VS + dB];
        ulonglong2 vA1 = *(const ulonglong2*)&vv[(j + 1) * VS + dA];
        ulonglong2 vB1 = *(const ulonglong2*)&vv[(j + 1) * VS + dB];
        ulonglong2 vA2 = *(const ulonglong2*)&vv[(j + 2) * VS + dA];
        ulonglong2 vB2 = *(const ulonglong2*)&vv[(j + 2) * VS + dB];
        ulonglong2 vA3 = *(const ulonglong2*)&vv[(j + 3) * VS + dA];
        ulonglong2 vB3 = *(const ulonglong2*)&vv[(j + 3) * VS + dB];
#pragma unroll
        for (int u = 0; u < 4; u++) {
            float4 a4 = *(const float4*)&attn[(c0 + u) * AS + j];
            u64t s0 = splat2(a4.x), s1 = splat2(a4.y);
            u64t s2 = splat2(a4.z), s3 = splat2(a4.w);
            ffma2(acc[u][0], s0, vA0.x); ffma2(acc[u][1], s0, vA0.y);
            ffma2(acc[u][2], s0, vB0.x); ffma2(acc[u][3], s0, vB0.y);
            ffma2(acc[u][0], s1, vA1.x); ffma2(acc[u][1], s1, vA1.y);
            ffma2(acc[u][2], s1, vB1.x); ffma2(acc[u][3], s1, vB1.y);
            ffma2(acc[u][0], s2, vA2.x); ffma2(acc[u][1], s2, vA2.y);
            ffma2(acc[u][2], s2, vB2.x); ffma2(acc[u][3], s2, vB2.y);
            ffma2(acc[u][0], s3, vA3.x); ffma2(acc[u][1], s3, vA3.y);
            ffma2(acc[u][2], s3, vB3.x); ffma2(acc[u][3], s3, vB3.y);
        }
    }

    float* og = out + ((size_t)b * TT + (size_t)n * CC) * DD;
#pragma unroll
    for (int u = 0; u < 4; u++) {
        int c = c0 + u;
        float inv = 1.0f / fmaxf(iz[c] + cz[c], 1.0f);
        float2 p0 = unpack2(acc[u][0]), p1 = unpack2(acc[u][1]);
        float2 p2 = unpack2(acc[u][2]), p3 = unpack2(acc[u][3]);
        float4 oA = {p0.x * inv, p0.y * inv, p1.x * inv, p1.y * inv};
        float4 oB = {p2.x * inv, p2.y * inv, p3.x * inv, p3.y * inv};
        *(float4*)&og[c * DD + dA] = oA;
        *(float4*)&og[c * DD + dB] = oB;
    }
}

// ---------------------------------------------------------------------------
extern "C" void kernel_launch(void* const* d_in, const int* in_sizes, int n_in,
                              void* d_out, int out_size)
{
    const float* q    = (const float*)d_in[0];
    const float* k    = (const float*)d_in[1];
    const float* v    = (const float*)d_in[2];
    const float* logd = (const float*)d_in[3];

    float* out = (float*)d_out;
    const size_t OUT_MAIN = (size_t)BB * TT * DD;            // 16777216
    const size_t OUT_ST   = (size_t)BB * DD * DD;            // 262144
    const size_t OUT_Z    = (size_t)BB * DD;                 // 2048
    int write_final = ((size_t)out_size >= OUT_MAIN + OUT_ST + OUT_Z) ? 1 : 0;
    float* out_state = out + OUT_MAIN;
    float* out_z     = out_state + OUT_ST;

    static bool attr_set = false;
    if (!attr_set) {
        cudaFuncSetAttribute(pass1_kernel,
                             cudaFuncAttributeMaxDynamicSharedMemorySize,
                             CC * DD * 2 * sizeof(float));             // 64 KB
        cudaFuncSetAttribute(pass3_kernel,
                             cudaFuncAttributeMaxDynamicSharedMemorySize,
                             P3_SMEM);                                 // ~84 KB
        attr_set = true;
    }

    pass1_kernel<<<BB * NN, 256, CC * DD * 2 * sizeof(float)>>>(k, v, logd);
    pass2_state_kernel<<<(BB * DD * DD) / 256, 256>>>(logd, out_state, write_final);
    pass2_z_kernel<<<(BB * DD) / 256, 256>>>(logd, out_z, write_final);
    pass3_kernel<<<BB * NN, 256, P3_SMEM>>>(q, k, v, logd, out);
}